// round 1
// baseline (speedup 1.0000x reference)
#include <cuda_runtime.h>

// CRF NLL: forward partition function (prob-domain with chunked renormalization)
// minus gold path score. B=64 batches, S=512 steps, T=64 states (62 tags + START=62 + END=63).
//
// Inputs (metadata order):
//   d_in[0] feats       float32 [B, S, T]
//   d_in[1] transitions float32 [T, T]   (trans[i*T+j] = score i -> j)
//   d_in[2] mask        int32   [B, S]   (contiguous prefix of ones)
//   d_in[3] tags        int32   [B, S]
// Output: float32 scalar = sum_b (forward_b - gold_b)

#define B_   64
#define S_   512
#define T_   64
#define CHUNK 8

__device__ float g_res[B_];

__global__ __launch_bounds__(64, 1) void crf_forward_kernel(
    const float* __restrict__ feats,
    const float* __restrict__ trans,
    const int*   __restrict__ mask,
    const int*   __restrict__ tags)
{
    __shared__ float trans_sh[T_ * T_];
    __shared__ float p_sh[2][T_];
    __shared__ float f_sh[CHUNK][T_];
    __shared__ int   tags_sh[S_];
    __shared__ float redf[2];
    __shared__ int   redi[2];

    const int b    = blockIdx.x;
    const int tid  = threadIdx.x;
    const int lane = tid & 31;
    const int warp = tid >> 5;

    const float* fb    = feats + (size_t)b * S_ * T_;
    const int*   maskb = mask  + b * S_;
    const int*   tagsb = tags  + b * S_;

    // ---- stage transitions (coalesced float4), tags, and compute len ----
    {
        const float4* t4 = (const float4*)trans;
        float4*       s4 = (float4*)trans_sh;
        #pragma unroll
        for (int i = 0; i < (T_ * T_ / 4); i += 64)
            s4[i + tid] = t4[i + tid];
    }
    int lenp = 0;
    #pragma unroll
    for (int k = 0; k < S_ / 64; ++k) {
        tags_sh[k * 64 + tid] = tagsb[k * 64 + tid];
        lenp += maskb[k * 64 + tid];
    }
    #pragma unroll
    for (int o = 16; o; o >>= 1) lenp += __shfl_xor_sync(0xffffffffu, lenp, o);
    if (lane == 0) redi[warp] = lenp;
    __syncthreads();
    const int len = redi[0] + redi[1];   // number of valid timesteps (>= 1)

    // ---- gold path score ----
    float g = 0.f;
    #pragma unroll 4
    for (int s = tid; s < S_; s += 64) {
        if (s < len) {
            int tg = tags_sh[s];
            int pv = (s == 0) ? (T_ - 2) : tags_sh[s - 1];
            g += fb[s * T_ + tg] + trans_sh[pv * T_ + tg];
        }
    }
    if (tid == 0) g += trans_sh[tags_sh[len - 1] * T_ + (T_ - 1)];  // end transition
    #pragma unroll
    for (int o = 16; o; o >>= 1) g += __shfl_xor_sync(0xffffffffu, g, o);
    if (lane == 0) redf[warp] = g;

    // ---- E[:,j] = exp(trans[:,j]) into registers (column of E per thread) ----
    float e[T_];
    #pragma unroll
    for (int i = 0; i < T_; ++i) e[i] = __expf(trans_sh[i * T_ + tid]);

    // ---- init: p_j = exp(f0_j + trans[START][j]) ----
    p_sh[0][tid] = __expf(fb[tid] + trans_sh[(T_ - 2) * T_ + tid]);
    __syncthreads();
    const float gold = redf[0] + redf[1];

    // ---- forward recurrence in probability domain ----
    int   cur    = 0;
    float logacc = 0.f;

    for (int c = 1; c < len; c += CHUNK) {
        const int cnt = min(CHUNK, len - c);

        // stage exp(f) for this chunk (coalesced; predicated tail)
        #pragma unroll
        for (int k = 0; k < CHUNK; ++k) {
            if (k < cnt) f_sh[k][tid] = __expf(fb[(c + k) * T_ + tid]);
        }

        // renormalize: Z = sum(p); fold 1/Z into first step's emission scale
        float z = 0.f;
        {
            const float4* pv = (const float4*)p_sh[cur];
            #pragma unroll
            for (int i = 0; i < T_ / 4; ++i) {
                float4 pp = pv[i];
                z += (pp.x + pp.y) + (pp.z + pp.w);
            }
        }
        float scale = 1.0f / z;
        logacc += logf(z);
        __syncthreads();   // f_sh visible; p reads done before next p writes

        for (int k = 0; k < cnt; ++k) {
            const float4* pv = (const float4*)p_sh[cur];
            float a0 = 0.f, a1 = 0.f, a2 = 0.f, a3 = 0.f;
            #pragma unroll
            for (int i = 0; i < T_ / 4; ++i) {
                float4 pp = pv[i];
                a0 = fmaf(pp.x, e[4 * i + 0], a0);
                a1 = fmaf(pp.y, e[4 * i + 1], a1);
                a2 = fmaf(pp.z, e[4 * i + 2], a2);
                a3 = fmaf(pp.w, e[4 * i + 3], a3);
            }
            float q = ((a0 + a1) + (a2 + a3)) * (f_sh[k][tid] * scale);
            p_sh[cur ^ 1][tid] = q;
            __syncthreads();
            cur ^= 1;
            scale = 1.0f;
        }
    }

    // ---- final transition into END: forward = logacc + log(sum_i p_i * exp(trans[i][END])) ----
    float v = p_sh[cur][tid] * __expf(trans_sh[tid * T_ + (T_ - 1)]);
    #pragma unroll
    for (int o = 16; o; o >>= 1) v += __shfl_xor_sync(0xffffffffu, v, o);
    if (lane == 0) redf[warp] = v;
    __syncthreads();
    if (tid == 0) {
        float forward = logacc + logf(redf[0] + redf[1]);
        g_res[b] = forward - gold;
    }
}

__global__ void crf_reduce_kernel(float* __restrict__ out)
{
    const int tid  = threadIdx.x;
    const int lane = tid & 31;
    const int warp = tid >> 5;
    __shared__ float sh[2];

    float v = g_res[tid];
    #pragma unroll
    for (int o = 16; o; o >>= 1) v += __shfl_xor_sync(0xffffffffu, v, o);
    if (lane == 0) sh[warp] = v;
    __syncthreads();
    if (tid == 0) out[0] = sh[0] + sh[1];
}

extern "C" void kernel_launch(void* const* d_in, const int* in_sizes, int n_in,
                              void* d_out, int out_size)
{
    const float* feats = (const float*)d_in[0];
    const float* trans = (const float*)d_in[1];
    const int*   mask  = (const int*)d_in[2];
    const int*   tags  = (const int*)d_in[3];
    float* out = (float*)d_out;

    crf_forward_kernel<<<B_, 64>>>(feats, trans, mask, tags);
    crf_reduce_kernel<<<1, 64>>>(out);
}

// round 2
// speedup vs baseline: 1.3760x; 1.3760x over previous
#include <cuda_runtime.h>

// CRF NLL, prob-domain forward with chunked renormalization.
// B=64, S=512, T=64 (62 tags + START=62 + END=63).
// R2: 256 threads/CTA (i-contraction split 4 ways, shfl-combined),
//     software-pipelined feats prefetch, 1 barrier per step.
//
// Inputs: d_in[0] feats f32 [B,S,T], d_in[1] transitions f32 [T,T],
//         d_in[2] mask i32 [B,S] (contiguous prefix), d_in[3] tags i32 [B,S]
// Output: f32 scalar sum_b (forward_b - gold_b)

#define B_    64
#define S_    512
#define T_    64
#define CHUNK 8

__device__ float g_res[B_];

__global__ __launch_bounds__(256, 1) void crf_forward_kernel(
    const float* __restrict__ feats,
    const float* __restrict__ trans,
    const int*   __restrict__ mask,
    const int*   __restrict__ tags)
{
    __shared__ float trans_sh[T_ * T_];
    __shared__ float p_sh[2][T_];
    __shared__ float f_sh[CHUNK][T_];
    __shared__ int   tags_sh[S_];
    __shared__ float redg[8];   // gold partials per warp
    __shared__ float redf[2];   // final END-transition partials
    __shared__ int   redi[8];   // length partials per warp

    const int b    = blockIdx.x;
    const int tid  = threadIdx.x;
    const int lane = tid & 31;
    const int warp = tid >> 5;
    const int seg  = lane >> 3;                 // 0..3 : i-segment of 16
    const int j    = (warp << 3) | (lane & 7);  // 0..63 : state column
    const int r    = tid >> 6;                  // 0..3 : staging row group
    const int col  = tid & 63;                  // staging column

    const float* fb    = feats + (size_t)b * S_ * T_;
    const int*   maskb = mask  + b * S_;
    const int*   tagsb = tags  + b * S_;

    // ---- stage transitions (coalesced float4: 4096 floats / 256 thr) ----
    {
        const float4* t4 = (const float4*)trans;
        float4*       s4 = (float4*)trans_sh;
        #pragma unroll
        for (int i = 0; i < 4; ++i) s4[i * 256 + tid] = t4[i * 256 + tid];
    }
    // ---- tags + length ----
    int lenp = 0;
    #pragma unroll
    for (int k = 0; k < 2; ++k) {
        tags_sh[k * 256 + tid] = tagsb[k * 256 + tid];
        lenp += maskb[k * 256 + tid];
    }
    #pragma unroll
    for (int o = 16; o; o >>= 1) lenp += __shfl_xor_sync(0xffffffffu, lenp, o);
    if (lane == 0) redi[warp] = lenp;
    __syncthreads();
    int len = 0;
    #pragma unroll
    for (int w = 0; w < 8; ++w) len += redi[w];

    // ---- gold path score (tags_sh/trans_sh visible after barrier) ----
    float g = 0.f;
    #pragma unroll
    for (int kk = 0; kk < 2; ++kk) {
        int s = kk * 256 + tid;
        if (s < len) {
            int tg = tags_sh[s];
            int pv = s ? tags_sh[s - 1] : (T_ - 2);
            g += fb[s * T_ + tg] + trans_sh[pv * T_ + tg];
        }
    }
    if (tid == 0) g += trans_sh[tags_sh[len - 1] * T_ + (T_ - 1)];
    #pragma unroll
    for (int o = 16; o; o >>= 1) g += __shfl_xor_sync(0xffffffffu, g, o);
    if (lane == 0) redg[warp] = g;

    // ---- E segment into registers: e[rr] = exp(trans[seg*16+rr][j]) ----
    float e[16];
    #pragma unroll
    for (int rr = 0; rr < 16; ++rr)
        e[rr] = __expf(trans_sh[(seg * 16 + rr) * T_ + j]);

    // ---- init p_0 ----
    if (tid < T_)
        p_sh[0][tid] = __expf(fb[tid] + trans_sh[(T_ - 2) * T_ + tid]);

    // ---- prefetch first chunk's feats (rows 1..8) into registers ----
    int c = 1;
    float fr0, fr1;
    {
        int r0 = min(c + r,     S_ - 1);
        int r1 = min(c + r + 4, S_ - 1);
        fr0 = fb[r0 * T_ + col];
        fr1 = fb[r1 * T_ + col];
    }
    __syncthreads();   // p_sh[0] + redg visible

    // ---- forward recurrence ----
    int   cur    = 0;
    float logacc = 0.f;

    while (c < len) {
        // stage exp(f) for this chunk from prefetched regs
        f_sh[r][col]     = __expf(fr0);
        f_sh[r + 4][col] = __expf(fr1);

        // prefetch next chunk
        int nc = c + CHUNK;
        if (nc < S_) {
            int r0 = min(nc + r,     S_ - 1);
            int r1 = min(nc + r + 4, S_ - 1);
            fr0 = fb[r0 * T_ + col];
            fr1 = fb[r1 * T_ + col];
        }

        // renormalize: z = sum(p) (broadcast LDS, tree add)
        float z;
        {
            const float4* pv4 = (const float4*)p_sh[cur];
            float z0 = 0.f, z1 = 0.f, z2 = 0.f, z3 = 0.f;
            #pragma unroll
            for (int i = 0; i < 16; i += 4) {
                float4 q0 = pv4[i],     q1 = pv4[i + 1];
                float4 q2 = pv4[i + 2], q3 = pv4[i + 3];
                z0 += (q0.x + q0.y) + (q0.z + q0.w);
                z1 += (q1.x + q1.y) + (q1.z + q1.w);
                z2 += (q2.x + q2.y) + (q2.z + q2.w);
                z3 += (q3.x + q3.y) + (q3.z + q3.w);
            }
            z = (z0 + z1) + (z2 + z3);
        }
        float scale = __fdividef(1.0f, z);
        logacc += __logf(z);

        const int cnt = min(CHUNK, len - c);
        __syncthreads();   // f_sh visible

        #pragma unroll
        for (int k = 0; k < CHUNK; ++k) {
            if (k >= cnt) break;   // cnt uniform across block
            const float4* pp4 = (const float4*)(p_sh[cur] + (seg << 4));
            float a0 = 0.f, a1 = 0.f, a2 = 0.f, a3 = 0.f;
            #pragma unroll
            for (int i = 0; i < 4; ++i) {
                float4 pp = pp4[i];
                a0 = fmaf(pp.x, e[4 * i + 0], a0);
                a1 = fmaf(pp.y, e[4 * i + 1], a1);
                a2 = fmaf(pp.z, e[4 * i + 2], a2);
                a3 = fmaf(pp.w, e[4 * i + 3], a3);
            }
            float v = (a0 + a1) + (a2 + a3);
            v += __shfl_xor_sync(0xffffffffu, v, 8);
            v += __shfl_xor_sync(0xffffffffu, v, 16);
            float q = v * f_sh[k][j];
            if (k == 0) q *= scale;
            if (seg == 0) p_sh[cur ^ 1][j] = q;
            __syncthreads();
            cur ^= 1;
        }
        c += CHUNK;
    }

    // ---- final transition into END ----
    if (tid < T_) {
        float v = p_sh[cur][tid] * __expf(trans_sh[tid * T_ + (T_ - 1)]);
        #pragma unroll
        for (int o = 16; o; o >>= 1) v += __shfl_xor_sync(0xffffffffu, v, o);
        if (lane == 0) redf[warp] = v;
    }
    __syncthreads();
    if (tid == 0) {
        float forward = logacc + __logf(redf[0] + redf[1]);
        float gold = 0.f;
        #pragma unroll
        for (int w = 0; w < 8; ++w) gold += redg[w];
        g_res[b] = forward - gold;
    }
}

__global__ void crf_reduce_kernel(float* __restrict__ out)
{
    const int tid  = threadIdx.x;
    const int lane = tid & 31;
    const int warp = tid >> 5;
    __shared__ float sh[2];

    float v = g_res[tid];
    #pragma unroll
    for (int o = 16; o; o >>= 1) v += __shfl_xor_sync(0xffffffffu, v, o);
    if (lane == 0) sh[warp] = v;
    __syncthreads();
    if (tid == 0) out[0] = sh[0] + sh[1];
}

extern "C" void kernel_launch(void* const* d_in, const int* in_sizes, int n_in,
                              void* d_out, int out_size)
{
    const float* feats = (const float*)d_in[0];
    const float* trans = (const float*)d_in[1];
    const int*   mask  = (const int*)d_in[2];
    const int*   tags  = (const int*)d_in[3];
    float* out = (float*)d_out;

    crf_forward_kernel<<<B_, 256>>>(feats, trans, mask, tags);
    crf_reduce_kernel<<<1, 64>>>(out);
}